// round 11
// baseline (speedup 1.0000x reference)
#include <cuda_runtime.h>
#include <cstdint>

#define NN 96
#define DD 64
#define TPB 256        // setup kernels
#define TPBP 128       // pair kernel: 4 warps, 4 pairs per CTA
#define NWP 4
#define NCHUNK 1200    // sum over U of ceil((U+1)/4)

// Scratch (allocation-free rule): device globals, recomputed deterministically every launch.
__device__ float g_X0[NN * DD];                        // z @ W1[:64]
__device__ float g_P0[NN * NN * DD];                   // [U][m][64]: base pre-activations
__device__ unsigned g_mask[NN * 3];                    // adjacency bitmask rows
__device__ __align__(16) unsigned char g_nbr[NN * NN]; // sorted neighbor lists

// bits [0, n) of 32-bit word w
__device__ __forceinline__ unsigned wmask(int n, int w) {
    int m = n - (w << 5);
    if (m <= 0) return 0u;
    if (m >= 32) return 0xffffffffu;
    return (1u << m) - 1u;
}

// cumulative 4-chunk count before U: U=4a+r -> U + 2a(a-1) + ra
__device__ __forceinline__ int cumc(int U) {
    int a = U >> 2, r = U & 3;
    return U + 2 * a * (a - 1) + r * a;
}

// blocks 0..95: X0 row; blocks 96..191: adjacency row (parallel compaction)
__global__ void setup_kernel(const float* __restrict__ z, const float* __restrict__ W1,
                             const float* __restrict__ adj) {
    if (blockIdx.x < NN) {
        int row = blockIdx.x, c = threadIdx.x;
        __shared__ float zr[DD];
        if (c < DD) zr[c] = z[row * DD + c];
        __syncthreads();
        if (c < DD) {
            float acc = 0.f;
#pragma unroll
            for (int k = 0; k < DD; k++) acc += zr[k] * W1[k * DD + c];
            g_X0[row * DD + c] = acc;
        }
    } else {
        int row = blockIdx.x - NN;
        int t = threadIdx.x;
        __shared__ unsigned smk[3];
        __shared__ unsigned char snb[NN];
        bool f = (adj[row * NN + t] != 0.0f);
        unsigned bal = __ballot_sync(0xffffffffu, f);
        if ((t & 31) == 0) { smk[t >> 5] = bal; g_mask[row * 3 + (t >> 5)] = bal; }
        snb[t] = 96;
        __syncthreads();
        unsigned m0 = smk[0], m1 = smk[1], m2 = smk[2];
        int w = t >> 5, l = t & 31;
        unsigned lm = (1u << l) - 1u;
        unsigned mw = (w == 0) ? m0 : ((w == 1) ? m1 : m2);
        int off = ((w > 0) ? __popc(m0) : 0) + ((w > 1) ? __popc(m1) : 0) + __popc(mw & lm);
        if (f) snb[off] = (unsigned char)t;
        __syncthreads();
        g_nbr[row * NN + t] = snb[t];
    }
}

// 2 blocks per U: P0[U][m] = sum_{b in Nbar(m) ∩ [0,U)} s0_b * x_b, for m < U.
__global__ void __launch_bounds__(TPB) setup_p0_kernel() {
    int U = blockIdx.x >> 1;
    int half = blockIdx.x & 1;
    __shared__ float yb[(NN + 1) * DD];   // s0_b * x_b for b<U, zero rows >= U and 96
    __shared__ float sS[NN];
    __shared__ unsigned sMask[NN * 3];
    int tid = threadIdx.x;
    int ln = tid & 15, hw = tid >> 4;

    for (int q = tid; q < NN * 3; q += TPB) sMask[q] = g_mask[q];
    __syncthreads();
    if (tid < NN) {
        int deg = 1 + __popc(sMask[tid * 3] & wmask(U, 0))
                    + __popc(sMask[tid * 3 + 1] & wmask(U, 1))
                    + __popc(sMask[tid * 3 + 2] & wmask(U, 2));
        sS[tid] = rsqrtf((float)deg);
    }
    __syncthreads();
    const float4* x04 = (const float4*)g_X0;
    for (int q = tid; q < (NN + 1) * 16; q += TPB) {
        int row = q >> 4;
        float4 v = make_float4(0.f, 0.f, 0.f, 0.f);
        if (row < U) {
            v = x04[q];
            float s = sS[row];
            v.x *= s; v.y *= s; v.z *= s; v.w *= s;
        }
        ((float4*)yb)[q] = v;
    }
    __syncthreads();

    const float4* yb4 = (const float4*)yb;
    float4* p04 = (float4*)g_P0;
    for (int m = hw + (half << 4); m < U; m += 32) {
        int cnt = __popc(sMask[m * 3] & wmask(U, 0))
                + __popc(sMask[m * 3 + 1] & wmask(U, 1))
                + __popc(sMask[m * 3 + 2] & wmask(U, 2));
        float4 a = yb4[m * 16 + ln];   // self term
        const unsigned char* lst = &g_nbr[m * NN];
        int c4 = (cnt + 3) & ~3;
        for (int q = 0; q < c4; q += 4) {
            unsigned pk = *(const unsigned*)(lst + q);   // entries >= cnt hit zero rows
            float4 y0 = yb4[((pk & 255u) << 4) + ln];
            a.x += y0.x; a.y += y0.y; a.z += y0.z; a.w += y0.w;
            float4 y1 = yb4[(((pk >> 8) & 255u) << 4) + ln];
            a.x += y1.x; a.y += y1.y; a.z += y1.z; a.w += y1.w;
            float4 y2 = yb4[(((pk >> 16) & 255u) << 4) + ln];
            a.x += y2.x; a.y += y2.y; a.z += y2.z; a.w += y2.w;
            float4 y3 = yb4[((pk >> 24) << 4) + ln];
            a.x += y3.x; a.y += y3.y; a.z += y3.z; a.w += y3.w;
        }
        p04[(U * NN + m) * 16 + ln] = a;
    }
}

// One CTA per (U, 4-L chunk); one warp per pair (L,U). Layer 2 fused inline.
// Deferred reduction + 2-target-per-half-warp unroll (MLP=2 on P0 loads).
__global__ void __launch_bounds__(TPBP) pair_kernel(const float* __restrict__ W1,
                                                    const float* __restrict__ W2,
                                                    float* __restrict__ out) {
    __shared__ unsigned sMask[NN * 3];
    __shared__ float sS0[NN], sS1d[NN];
    __shared__ float sX[NN * DD];            // x rows staged for b in N(U)∩[0,U), b-indexed
    __shared__ unsigned char sTl[NWP][NN];   // per-warp target list

    // block -> (U, Lbase); reversed so heavy chunks first
    int b = (NCHUNK - 1) - (int)blockIdx.x;
    int U = (int)(sqrtf(8.0f * (float)b) * 0.5f);
    if (U > 95) U = 95;
    while (U < 95 && cumc(U + 1) <= b) ++U;
    while (U > 0 && cumc(U) > b) --U;
    int Lbase = (b - cumc(U)) * NWP;

    int tid = threadIdx.x;
    int lane = tid & 31, warp = tid >> 5;

    for (int q = tid; q < NN * 3; q += TPBP) sMask[q] = g_mask[q];
    __syncthreads();

    unsigned uw0 = sMask[U * 3 + 0] & wmask(U, 0);
    unsigned uw1 = sMask[U * 3 + 1] & wmask(U, 1);
    unsigned uw2 = sMask[U * 3 + 2] & wmask(U, 2);
    int cntU = __popc(uw0) + __popc(uw1) + __popc(uw2);

    if (tid < NN) {
        int m = tid;
        int deg = 1 + __popc(sMask[m * 3] & wmask(U, 0))
                    + __popc(sMask[m * 3 + 1] & wmask(U, 1))
                    + __popc(sMask[m * 3 + 2] & wmask(U, 2));
        float s0 = rsqrtf((float)deg);
        sS0[m] = s0;
        sS1d[m] = rsqrtf((float)(deg + 1)) - s0;
    }
    // stage x rows for b in N(U)∩[0,U)  (covers every warp's D set)
    const float4* x04 = (const float4*)g_X0;
    for (int q = tid >> 4; q < cntU; q += TPBP / 16) {
        int bb = g_nbr[U * NN + q];
        ((float4*)sX)[bb * 16 + (tid & 15)] = x04[bb * 16 + (tid & 15)];
    }
    __syncthreads();

    int L = Lbase + warp;
    if (L > U) return;

    // ---- per-warp pair (L, U) ----
    unsigned Dw0 = sMask[U * 3 + 0] & wmask(L, 0);
    unsigned Dw1 = sMask[U * 3 + 1] & wmask(L, 1);
    unsigned Dw2 = sMask[U * 3 + 2] & wmask(L, 2);
    int nD = __popc(Dw0) + __popc(Dw1) + __popc(Dw2);
    float sU = rsqrtf(1.0f + (float)nD);
    float sL0 = sS0[L];

    // target words: (Nbar(L)∩[0,U)) ∪ D ∪ {U}
    unsigned t0 = ((sMask[L * 3 + 0] | ((L < 32) ? (1u << L) : 0u)) & wmask(U, 0)) | Dw0;
    unsigned t1 = ((sMask[L * 3 + 1] | ((L >= 32 && L < 64) ? (1u << (L & 31)) : 0u)) & wmask(U, 1)) | Dw1;
    unsigned t2 = ((sMask[L * 3 + 2] | ((L >= 64) ? (1u << (L & 31)) : 0u)) & wmask(U, 2)) | Dw2;
    if (U < 32) t0 |= 1u << U; else if (U < 64) t1 |= 1u << (U & 31); else t2 |= 1u << (U & 31);

    // ballot-free compaction (t words uniform across warp)
    unsigned lm = (1u << lane) - 1u;
    int c0 = __popc(t0), c1 = __popc(t1);
    if ((t0 >> lane) & 1) sTl[warp][__popc(t0 & lm)] = (unsigned char)lane;
    if ((t1 >> lane) & 1) sTl[warp][c0 + __popc(t1 & lm)] = (unsigned char)(32 + lane);
    if ((t2 >> lane) & 1) sTl[warp][c0 + c1 + __popc(t2 & lm)] = (unsigned char)(64 + lane);
    int nT = c0 + c1 + __popc(t2);
    __syncwarp();

    // per-lane constants (float4 slice ln)
    int ln = lane & 15, h = lane >> 4;
    const float4* W14 = (const float4*)W1;
    float4 w2v = __ldg(&((const float4*)W2)[ln]);
    float4 paV = __ldg(&W14[64 * 16 + ln]);
    float4 pbV = __ldg(&W14[65 * 16 + ln]);
    float4 dv = make_float4(pbV.x - paV.x, pbV.y - paV.y, pbV.z - paV.z, pbV.w - paV.w);
    float4 yU = __ldg(&x04[U * 16 + ln]);
    yU.x += pbV.x; yU.y += pbV.y; yU.z += pbV.z; yU.w += pbV.w;
    if (L == U) { yU.x += paV.x; yU.y += paV.y; yU.z += paV.z; yU.w += paV.w; }

    const float4* p04 = (const float4*)g_P0;
    float acc1 = 0.f, acc2 = 0.f;

    // body for one target m with pre-loaded base row P
    auto process = [&](int m, bool act, float4 P) {
        bool isU = (m == U);
        // scale-bump corrections over b in Nbar(m) ∩ D (s1-s0), +s0 if m==U (full s1 weight)
        int mw = m >> 5;
        unsigned mb = 1u << (m & 31);
#pragma unroll
        for (int w = 0; w < 3; w++) {
            unsigned cm = sMask[m * 3 + w] | ((mw == w) ? mb : 0u);
            cm &= (w == 0) ? Dw0 : ((w == 1) ? Dw1 : Dw2);
            while (cm) {
                int bb = __ffs(cm) - 1;
                cm &= cm - 1;
                bb += w << 5;
                float wt = sS1d[bb] + (isU ? sS0[bb] : 0.f);
                float4 xb = ((const float4*)sX)[bb * 16 + ln];
                P.x += wt * xb.x; P.y += wt * xb.y; P.z += wt * xb.z; P.w += wt * xb.w;
            }
        }

        unsigned dwm = (mw == 0) ? Dw0 : ((mw == 1) ? Dw1 : Dw2);
        bool inD  = !isU && ((dwm & mb) != 0);
        bool inNL = (m == L) || ((sMask[L * 3 + mw] & mb) != 0);

        if (L != U && !isU && inNL) {   // node L's w64 perturbation (scale s0_L)
            P.x += sL0 * paV.x; P.y += sL0 * paV.y; P.z += sL0 * paV.z; P.w += sL0 * paV.w;
        }
        if (isU || inD) {               // U term: s_U * y_U
            P.x += sU * yU.x; P.y += sU * yU.y; P.z += sU * yU.z; P.w += sU * yU.w;
        }

        float sm = isU ? sU : (sS0[m] + (inD ? sS1d[m] : 0.f));
        float c = (L == U) ? 0.f : (isU ? -sU : ((inNL ? sL0 : 0.f) - (inD ? sU : 0.f)));

        float g1 = fmaxf(sm * P.x, 0.f) * w2v.x + fmaxf(sm * P.y, 0.f) * w2v.y
                 + fmaxf(sm * P.z, 0.f) * w2v.z + fmaxf(sm * P.w, 0.f) * w2v.w;
        float g2 = fmaxf(sm * (P.x + c * dv.x), 0.f) * w2v.x
                 + fmaxf(sm * (P.y + c * dv.y), 0.f) * w2v.y
                 + fmaxf(sm * (P.z + c * dv.z), 0.f) * w2v.z
                 + fmaxf(sm * (P.w + c * dv.w), 0.f) * w2v.w;

        // fused layer 2: coef = s_L*pa[L,m] + s_U*pa[U,m]
        float coef = 0.f;
        if (act) {
            if (isU) coef = (L == U) ? 2.f * sU : sU;
            else     coef = (inNL ? sL0 : 0.f) + (inD ? sU : 0.f);
        }
        coef *= sm;
        acc1 += coef * g1;
        acc2 += coef * g2;
    };

    // 2 targets per half-warp per round: both LDS + both LDGs issue up front (MLP=2)
    int rounds = (nT + 3) >> 2;
    for (int r = 0; r < rounds; r++) {
        int idxA = 4 * r + h;
        int idxB = idxA + 2;
        bool actA = (idxA < nT), actB = (idxB < nT);
        int mA = sTl[warp][actA ? idxA : 0];
        int mB = sTl[warp][actB ? idxB : 0];
        float4 PA = make_float4(0.f, 0.f, 0.f, 0.f);
        float4 PB = make_float4(0.f, 0.f, 0.f, 0.f);
        if (mA != U) PA = __ldg(&p04[(U * NN + mA) * 16 + ln]);
        if (mB != U) PB = __ldg(&p04[(U * NN + mB) * 16 + ln]);
        process(mA, actA, PA);
        process(mB, actB, PB);
    }

    // single full-warp reduction (sums 16 lanes per half AND both halves' targets)
#pragma unroll
    for (int off = 16; off; off >>= 1) {
        acc1 += __shfl_xor_sync(0xffffffffu, acc1, off);
        acc2 += __shfl_xor_sync(0xffffffffu, acc2, off);
    }
    if (lane == 0) {
        out[L * NN + U] = acc1;
        out[U * NN + L] = acc2;
    }
}

extern "C" void kernel_launch(void* const* d_in, const int* in_sizes, int n_in,
                              void* d_out, int out_size) {
    const float* z   = (const float*)d_in[0];
    const float* adj = (const float*)d_in[1];
    const float* W1  = (const float*)d_in[2];
    const float* W2  = (const float*)d_in[3];
    float* out = (float*)d_out;

    setup_kernel<<<2 * NN, NN>>>(z, W1, adj);
    setup_p0_kernel<<<2 * NN, TPB>>>();
    pair_kernel<<<NCHUNK, TPBP>>>(W1, W2, out);
}

// round 13
// speedup vs baseline: 1.0077x; 1.0077x over previous
#include <cuda_runtime.h>
#include <cstdint>

#define NN 96
#define DD 64
#define TPB 256
#define NCHUNK 624   // sum over U of ceil((U+1)/8)

// Scratch (allocation-free rule): device globals, recomputed deterministically every launch.
__device__ float g_X0[NN * DD];                        // z @ W1[:64]
__device__ float g_P0[NN * NN * DD];                   // [U][m][64]: base pre-activations
__device__ unsigned g_mask[NN * 3];                    // adjacency bitmask rows
__device__ __align__(16) unsigned char g_nbr[NN * NN]; // sorted neighbor lists

// bits [0, n) of 32-bit word w
__device__ __forceinline__ unsigned wmask(int n, int w) {
    int m = n - (w << 5);
    if (m <= 0) return 0u;
    if (m >= 32) return 0xffffffffu;
    return (1u << m) - 1u;
}

// cumulative chunk count before U: U=8a+r -> (a+1)(4a+r)
__device__ __forceinline__ int cumc(int U) {
    int a = U >> 3, r = U & 7;
    return (a + 1) * (4 * a + r);
}

// blocks 0..95: X0 row; blocks 96..191: adjacency row (parallel compaction)
__global__ void setup_kernel(const float* __restrict__ z, const float* __restrict__ W1,
                             const float* __restrict__ adj) {
    if (blockIdx.x < NN) {
        int row = blockIdx.x, c = threadIdx.x;
        __shared__ float zr[DD];
        if (c < DD) zr[c] = z[row * DD + c];
        __syncthreads();
        if (c < DD) {
            float acc = 0.f;
#pragma unroll
            for (int k = 0; k < DD; k++) acc += zr[k] * W1[k * DD + c];
            g_X0[row * DD + c] = acc;
        }
    } else {
        int row = blockIdx.x - NN;
        int t = threadIdx.x;
        __shared__ unsigned smk[3];
        __shared__ unsigned char snb[NN];
        bool f = (adj[row * NN + t] != 0.0f);
        unsigned bal = __ballot_sync(0xffffffffu, f);
        if ((t & 31) == 0) { smk[t >> 5] = bal; g_mask[row * 3 + (t >> 5)] = bal; }
        snb[t] = 96;
        __syncthreads();
        unsigned m0 = smk[0], m1 = smk[1], m2 = smk[2];
        int w = t >> 5, l = t & 31;
        unsigned lm = (1u << l) - 1u;
        unsigned mw = (w == 0) ? m0 : ((w == 1) ? m1 : m2);
        int off = ((w > 0) ? __popc(m0) : 0) + ((w > 1) ? __popc(m1) : 0) + __popc(mw & lm);
        if (f) snb[off] = (unsigned char)t;
        __syncthreads();
        g_nbr[row * NN + t] = snb[t];
    }
}

// 2 blocks per U: P0[U][m] = sum_{b in Nbar(m) ∩ [0,U)} s0_b * x_b, for m < U.
__global__ void __launch_bounds__(TPB) setup_p0_kernel() {
    int U = blockIdx.x >> 1;
    int half = blockIdx.x & 1;
    __shared__ float yb[(NN + 1) * DD];   // s0_b * x_b for b<U, zero rows >= U and 96
    __shared__ float sS[NN];
    __shared__ unsigned sMask[NN * 3];
    int tid = threadIdx.x;
    int ln = tid & 15, hw = tid >> 4;

    for (int q = tid; q < NN * 3; q += TPB) sMask[q] = g_mask[q];
    __syncthreads();
    if (tid < NN) {
        int deg = 1 + __popc(sMask[tid * 3] & wmask(U, 0))
                    + __popc(sMask[tid * 3 + 1] & wmask(U, 1))
                    + __popc(sMask[tid * 3 + 2] & wmask(U, 2));
        sS[tid] = rsqrtf((float)deg);
    }
    __syncthreads();
    const float4* x04 = (const float4*)g_X0;
    for (int q = tid; q < (NN + 1) * 16; q += TPB) {
        int row = q >> 4;
        float4 v = make_float4(0.f, 0.f, 0.f, 0.f);
        if (row < U) {
            v = x04[q];
            float s = sS[row];
            v.x *= s; v.y *= s; v.z *= s; v.w *= s;
        }
        ((float4*)yb)[q] = v;
    }
    __syncthreads();

    const float4* yb4 = (const float4*)yb;
    float4* p04 = (float4*)g_P0;
    for (int m = hw + (half << 4); m < U; m += 32) {
        int cnt = __popc(sMask[m * 3] & wmask(U, 0))
                + __popc(sMask[m * 3 + 1] & wmask(U, 1))
                + __popc(sMask[m * 3 + 2] & wmask(U, 2));
        float4 a = yb4[m * 16 + ln];   // self term
        const unsigned char* lst = &g_nbr[m * NN];
        int c4 = (cnt + 3) & ~3;
        for (int q = 0; q < c4; q += 4) {
            unsigned pk = *(const unsigned*)(lst + q);   // entries >= cnt hit zero rows
            float4 y0 = yb4[((pk & 255u) << 4) + ln];
            a.x += y0.x; a.y += y0.y; a.z += y0.z; a.w += y0.w;
            float4 y1 = yb4[(((pk >> 8) & 255u) << 4) + ln];
            a.x += y1.x; a.y += y1.y; a.z += y1.z; a.w += y1.w;
            float4 y2 = yb4[(((pk >> 16) & 255u) << 4) + ln];
            a.x += y2.x; a.y += y2.y; a.z += y2.z; a.w += y2.w;
            float4 y3 = yb4[((pk >> 24) << 4) + ln];
            a.x += y3.x; a.y += y3.y; a.z += y3.z; a.w += y3.w;
        }
        p04[(U * NN + m) * 16 + ln] = a;
    }
}

// One CTA per (U, 8-L chunk); one warp per pair (L,U). Layer 2 fused inline.
// Deferred reduction; P0[U] staged in STATIC smem; corrections read X0 via L1.
__global__ void __launch_bounds__(TPB) pair_kernel(const float* __restrict__ W1,
                                                   const float* __restrict__ W2,
                                                   float* __restrict__ out) {
    __shared__ float sP0[NN * DD];           // P0[U][m] rows, m < U  (24.6 KB)
    __shared__ unsigned sMask[NN * 3];
    __shared__ float sS0[NN], sS1d[NN];
    __shared__ unsigned char sTl[8][NN];     // per-warp target list

    // block -> (U, Lbase); reversed so heavy chunks first
    int b = (NCHUNK - 1) - (int)blockIdx.x;
    int a0 = (int)(sqrtf((float)b) * 0.5f);
    int U = 8 * a0;
    if (U > 95) U = 95;
    while (U < 95 && cumc(U + 1) <= b) ++U;
    while (U > 0 && cumc(U) > b) --U;
    int Lbase = (b - cumc(U)) * 8;

    int tid = threadIdx.x;
    int lane = tid & 31, warp = tid >> 5;

    for (int q = tid; q < NN * 3; q += TPB) sMask[q] = g_mask[q];
    // bulk-stage P0[U] rows 0..U-1 (coalesced, high MLP; same barrier as mask load)
    const float4* p04g = (const float4*)g_P0 + (size_t)U * NN * 16;
    for (int q = tid; q < U * 16; q += TPB) ((float4*)sP0)[q] = p04g[q];
    if (tid < NN) {
        int m = tid;
        unsigned gm0 = __ldg(&g_mask[m * 3 + 0]), gm1 = __ldg(&g_mask[m * 3 + 1]),
                 gm2 = __ldg(&g_mask[m * 3 + 2]);
        int deg = 1 + __popc(gm0 & wmask(U, 0)) + __popc(gm1 & wmask(U, 1))
                    + __popc(gm2 & wmask(U, 2));
        float s0 = rsqrtf((float)deg);
        sS0[m] = s0;
        sS1d[m] = rsqrtf((float)(deg + 1)) - s0;
    }
    __syncthreads();

    int L = Lbase + warp;
    if (L > U) return;

    // ---- per-warp pair (L, U) ----
    unsigned Dw0 = sMask[U * 3 + 0] & wmask(L, 0);
    unsigned Dw1 = sMask[U * 3 + 1] & wmask(L, 1);
    unsigned Dw2 = sMask[U * 3 + 2] & wmask(L, 2);
    int nD = __popc(Dw0) + __popc(Dw1) + __popc(Dw2);
    float sU = rsqrtf(1.0f + (float)nD);
    float sL0 = sS0[L];

    // target words: (Nbar(L)∩[0,U)) ∪ D ∪ {U}
    unsigned t0 = ((sMask[L * 3 + 0] | ((L < 32) ? (1u << L) : 0u)) & wmask(U, 0)) | Dw0;
    unsigned t1 = ((sMask[L * 3 + 1] | ((L >= 32 && L < 64) ? (1u << (L & 31)) : 0u)) & wmask(U, 1)) | Dw1;
    unsigned t2 = ((sMask[L * 3 + 2] | ((L >= 64) ? (1u << (L & 31)) : 0u)) & wmask(U, 2)) | Dw2;
    if (U < 32) t0 |= 1u << U; else if (U < 64) t1 |= 1u << (U & 31); else t2 |= 1u << (U & 31);

    // ballot-free compaction (t words uniform across warp)
    unsigned lm = (1u << lane) - 1u;
    int c0 = __popc(t0), c1 = __popc(t1);
    if ((t0 >> lane) & 1) sTl[warp][__popc(t0 & lm)] = (unsigned char)lane;
    if ((t1 >> lane) & 1) sTl[warp][c0 + __popc(t1 & lm)] = (unsigned char)(32 + lane);
    if ((t2 >> lane) & 1) sTl[warp][c0 + c1 + __popc(t2 & lm)] = (unsigned char)(64 + lane);
    int nT = c0 + c1 + __popc(t2);
    __syncwarp();

    // per-lane constants (float4 slice ln)
    int ln = lane & 15, h = lane >> 4;
    const float4* W14 = (const float4*)W1;
    const float4* x04 = (const float4*)g_X0;
    float4 w2v = __ldg(&((const float4*)W2)[ln]);
    float4 paV = __ldg(&W14[64 * 16 + ln]);
    float4 pbV = __ldg(&W14[65 * 16 + ln]);
    float4 dv = make_float4(pbV.x - paV.x, pbV.y - paV.y, pbV.z - paV.z, pbV.w - paV.w);
    float4 yU = __ldg(&x04[U * 16 + ln]);
    yU.x += pbV.x; yU.y += pbV.y; yU.z += pbV.z; yU.w += pbV.w;
    if (L == U) { yU.x += paV.x; yU.y += paV.y; yU.z += paV.z; yU.w += paV.w; }

    float acc1 = 0.f, acc2 = 0.f;
    int rounds = (nT + 1) >> 1;

    for (int r = 0; r < rounds; r++) {
        int idx = 2 * r + h;
        bool act = (idx < nT);
        int m = sTl[warp][act ? idx : 0];
        bool isU = (m == U);

        float4 P = make_float4(0.f, 0.f, 0.f, 0.f);
        if (!isU) P = ((const float4*)sP0)[m * 16 + ln];   // smem, 29-cyc latency

        // scale-bump corrections over b in Nbar(m) ∩ D (s1-s0), +s0 if m==U (full s1 weight)
        int mw = m >> 5;
        unsigned mb = 1u << (m & 31);
#pragma unroll
        for (int w = 0; w < 3; w++) {
            unsigned cm = sMask[m * 3 + w] | ((mw == w) ? mb : 0u);
            cm &= (w == 0) ? Dw0 : ((w == 1) ? Dw1 : Dw2);
            while (cm) {
                int bb = __ffs(cm) - 1;
                cm &= cm - 1;
                bb += w << 5;
                float wt = sS1d[bb] + (isU ? sS0[bb] : 0.f);
                float4 xb = __ldg(&x04[bb * 16 + ln]);    // X0: 24 KB, L1-resident
                P.x += wt * xb.x; P.y += wt * xb.y; P.z += wt * xb.z; P.w += wt * xb.w;
            }
        }

        unsigned dwm = (mw == 0) ? Dw0 : ((mw == 1) ? Dw1 : Dw2);
        bool inD  = !isU && ((dwm & mb) != 0);
        bool inNL = (m == L) || ((sMask[L * 3 + mw] & mb) != 0);

        if (L != U && !isU && inNL) {   // node L's w64 perturbation (scale s0_L)
            P.x += sL0 * paV.x; P.y += sL0 * paV.y; P.z += sL0 * paV.z; P.w += sL0 * paV.w;
        }
        if (isU || inD) {               // U term: s_U * y_U
            P.x += sU * yU.x; P.y += sU * yU.y; P.z += sU * yU.z; P.w += sU * yU.w;
        }

        float sm = isU ? sU : (sS0[m] + (inD ? sS1d[m] : 0.f));
        float c = (L == U) ? 0.f : (isU ? -sU : ((inNL ? sL0 : 0.f) - (inD ? sU : 0.f)));

        // per-lane partial g (reduction deferred to warp end)
        float g1 = fmaxf(sm * P.x, 0.f) * w2v.x + fmaxf(sm * P.y, 0.f) * w2v.y
                 + fmaxf(sm * P.z, 0.f) * w2v.z + fmaxf(sm * P.w, 0.f) * w2v.w;
        float g2 = fmaxf(sm * (P.x + c * dv.x), 0.f) * w2v.x
                 + fmaxf(sm * (P.y + c * dv.y), 0.f) * w2v.y
                 + fmaxf(sm * (P.z + c * dv.z), 0.f) * w2v.z
                 + fmaxf(sm * (P.w + c * dv.w), 0.f) * w2v.w;

        // fused layer 2: coef = s_L*pa[L,m] + s_U*pa[U,m]
        float coef = 0.f;
        if (act) {
            if (isU) coef = (L == U) ? 2.f * sU : sU;
            else     coef = (inNL ? sL0 : 0.f) + (inD ? sU : 0.f);
        }
        coef *= sm;
        acc1 += coef * g1;
        acc2 += coef * g2;
    }

    // single full-warp reduction (sums 16 lanes per half AND both halves' targets)
#pragma unroll
    for (int off = 16; off; off >>= 1) {
        acc1 += __shfl_xor_sync(0xffffffffu, acc1, off);
        acc2 += __shfl_xor_sync(0xffffffffu, acc2, off);
    }
    if (lane == 0) {
        out[L * NN + U] = acc1;
        out[U * NN + L] = acc2;
    }
}

extern "C" void kernel_launch(void* const* d_in, const int* in_sizes, int n_in,
                              void* d_out, int out_size) {
    const float* z   = (const float*)d_in[0];
    const float* adj = (const float*)d_in[1];
    const float* W1  = (const float*)d_in[2];
    const float* W2  = (const float*)d_in[3];
    float* out = (float*)d_out;

    setup_kernel<<<2 * NN, NN>>>(z, W1, adj);
    setup_p0_kernel<<<2 * NN, TPB>>>();
    pair_kernel<<<NCHUNK, TPB>>>(W1, W2, out);
}

// round 14
// speedup vs baseline: 1.1440x; 1.1352x over previous
#include <cuda_runtime.h>
#include <cstdint>

#define NN 96
#define DD 64
#define TPB 256
#define NCHUNK 624   // sum over U of ceil((U+1)/8)

// Scratch (allocation-free rule): device globals, recomputed deterministically every launch.
__device__ float g_X0[NN * DD];                        // z @ W1[:64]
__device__ float g_P0[NN * NN * DD];                   // [U][m][64]: base pre-activations
__device__ unsigned g_mask[NN * 3];                    // adjacency bitmask rows
__device__ __align__(16) unsigned char g_nbr[NN * NN]; // sorted neighbor lists

// bits [0, n) of 32-bit word w
__device__ __forceinline__ unsigned wmask(int n, int w) {
    int m = n - (w << 5);
    if (m <= 0) return 0u;
    if (m >= 32) return 0xffffffffu;
    return (1u << m) - 1u;
}

// cumulative chunk count before U: U=8a+r -> (a+1)(4a+r)
__device__ __forceinline__ int cumc(int U) {
    int a = U >> 3, r = U & 7;
    return (a + 1) * (4 * a + r);
}

// blocks 0..95: X0 row; blocks 96..191: adjacency row (parallel compaction)
__global__ void setup_kernel(const float* __restrict__ z, const float* __restrict__ W1,
                             const float* __restrict__ adj) {
    if (blockIdx.x < NN) {
        int row = blockIdx.x, c = threadIdx.x;
        __shared__ float zr[DD];
        if (c < DD) zr[c] = z[row * DD + c];
        __syncthreads();
        if (c < DD) {
            float acc = 0.f;
#pragma unroll
            for (int k = 0; k < DD; k++) acc += zr[k] * W1[k * DD + c];
            g_X0[row * DD + c] = acc;
        }
    } else {
        int row = blockIdx.x - NN;
        int t = threadIdx.x;
        __shared__ unsigned smk[3];
        __shared__ unsigned char snb[NN];
        bool f = (adj[row * NN + t] != 0.0f);
        unsigned bal = __ballot_sync(0xffffffffu, f);
        if ((t & 31) == 0) { smk[t >> 5] = bal; g_mask[row * 3 + (t >> 5)] = bal; }
        snb[t] = 96;
        __syncthreads();
        unsigned m0 = smk[0], m1 = smk[1], m2 = smk[2];
        int w = t >> 5, l = t & 31;
        unsigned lm = (1u << l) - 1u;
        unsigned mw = (w == 0) ? m0 : ((w == 1) ? m1 : m2);
        int off = ((w > 0) ? __popc(m0) : 0) + ((w > 1) ? __popc(m1) : 0) + __popc(mw & lm);
        if (f) snb[off] = (unsigned char)t;
        __syncthreads();
        g_nbr[row * NN + t] = snb[t];
    }
}

// 2 blocks per U: P0[U][m] = sum_{b in Nbar(m) ∩ [0,U)} s0_b * x_b, for m < U.
__global__ void __launch_bounds__(TPB) setup_p0_kernel() {
    int U = blockIdx.x >> 1;
    int half = blockIdx.x & 1;
    __shared__ float yb[(NN + 1) * DD];   // s0_b * x_b for b<U, zero rows >= U and 96
    __shared__ float sS[NN];
    __shared__ unsigned sMask[NN * 3];
    int tid = threadIdx.x;
    int ln = tid & 15, hw = tid >> 4;

    for (int q = tid; q < NN * 3; q += TPB) sMask[q] = g_mask[q];
    __syncthreads();
    if (tid < NN) {
        int deg = 1 + __popc(sMask[tid * 3] & wmask(U, 0))
                    + __popc(sMask[tid * 3 + 1] & wmask(U, 1))
                    + __popc(sMask[tid * 3 + 2] & wmask(U, 2));
        sS[tid] = rsqrtf((float)deg);
    }
    __syncthreads();
    const float4* x04 = (const float4*)g_X0;
    for (int q = tid; q < (NN + 1) * 16; q += TPB) {
        int row = q >> 4;
        float4 v = make_float4(0.f, 0.f, 0.f, 0.f);
        if (row < U) {
            v = x04[q];
            float s = sS[row];
            v.x *= s; v.y *= s; v.z *= s; v.w *= s;
        }
        ((float4*)yb)[q] = v;
    }
    __syncthreads();

    const float4* yb4 = (const float4*)yb;
    float4* p04 = (float4*)g_P0;
    for (int m = hw + (half << 4); m < U; m += 32) {
        int cnt = __popc(sMask[m * 3] & wmask(U, 0))
                + __popc(sMask[m * 3 + 1] & wmask(U, 1))
                + __popc(sMask[m * 3 + 2] & wmask(U, 2));
        float4 a = yb4[m * 16 + ln];   // self term
        const unsigned char* lst = &g_nbr[m * NN];
        int c4 = (cnt + 3) & ~3;
        for (int q = 0; q < c4; q += 4) {
            unsigned pk = *(const unsigned*)(lst + q);   // entries >= cnt hit zero rows
            float4 y0 = yb4[((pk & 255u) << 4) + ln];
            a.x += y0.x; a.y += y0.y; a.z += y0.z; a.w += y0.w;
            float4 y1 = yb4[(((pk >> 8) & 255u) << 4) + ln];
            a.x += y1.x; a.y += y1.y; a.z += y1.z; a.w += y1.w;
            float4 y2 = yb4[(((pk >> 16) & 255u) << 4) + ln];
            a.x += y2.x; a.y += y2.y; a.z += y2.z; a.w += y2.w;
            float4 y3 = yb4[((pk >> 24) << 4) + ln];
            a.x += y3.x; a.y += y3.y; a.z += y3.z; a.w += y3.w;
        }
        p04[(U * NN + m) * 16 + ln] = a;
    }
}

// One CTA per (U, 8-L chunk); one warp per pair (L,U). Layer 2 fused inline.
// Deferred reduction; per-target scalar work hoisted to lane-parallel precompute (sMeta).
__global__ void __launch_bounds__(TPB) pair_kernel(const float* __restrict__ W1,
                                                   const float* __restrict__ W2,
                                                   float* __restrict__ out) {
    __shared__ unsigned sMask[NN * 3];
    __shared__ float sS0[NN], sS1d[NN];
    __shared__ float sX[NN * DD];            // x rows staged for b in N(U)∩[0,U), b-indexed
    __shared__ float4 sMeta[8][NN];          // per-warp: (sm, c, coef, pack{m,inD,inNL})

    // block -> (U, Lbase); reversed so heavy chunks first
    int b = (NCHUNK - 1) - (int)blockIdx.x;
    int a0 = (int)(sqrtf((float)b) * 0.5f);
    int U = 8 * a0;
    if (U > 95) U = 95;
    while (U < 95 && cumc(U + 1) <= b) ++U;
    while (U > 0 && cumc(U) > b) --U;
    int Lbase = (b - cumc(U)) * 8;

    int tid = threadIdx.x;
    int lane = tid & 31, warp = tid >> 5;

    for (int q = tid; q < NN * 3; q += TPB) sMask[q] = g_mask[q];
    __syncthreads();

    unsigned uw0 = sMask[U * 3 + 0] & wmask(U, 0);
    unsigned uw1 = sMask[U * 3 + 1] & wmask(U, 1);
    unsigned uw2 = sMask[U * 3 + 2] & wmask(U, 2);
    int cntU = __popc(uw0) + __popc(uw1) + __popc(uw2);

    if (tid < NN) {
        int m = tid;
        int deg = 1 + __popc(sMask[m * 3] & wmask(U, 0))
                    + __popc(sMask[m * 3 + 1] & wmask(U, 1))
                    + __popc(sMask[m * 3 + 2] & wmask(U, 2));
        float s0 = rsqrtf((float)deg);
        sS0[m] = s0;
        sS1d[m] = rsqrtf((float)(deg + 1)) - s0;
    }
    // stage x rows for b in N(U)∩[0,U)  (covers every warp's D set)
    const float4* x04 = (const float4*)g_X0;
    for (int q = tid >> 4; q < cntU; q += 16) {
        int bb = g_nbr[U * NN + q];
        ((float4*)sX)[bb * 16 + (tid & 15)] = x04[bb * 16 + (tid & 15)];
    }
    __syncthreads();

    int L = Lbase + warp;
    if (L > U) return;

    // ---- per-warp pair (L, U) ----
    unsigned Dw0 = sMask[U * 3 + 0] & wmask(L, 0);
    unsigned Dw1 = sMask[U * 3 + 1] & wmask(L, 1);
    unsigned Dw2 = sMask[U * 3 + 2] & wmask(L, 2);
    int nD = __popc(Dw0) + __popc(Dw1) + __popc(Dw2);
    float sU = rsqrtf(1.0f + (float)nD);
    float sL0 = sS0[L];

    // target words: (Nbar(L)∩[0,U)) ∪ D ∪ {U}
    unsigned t0 = ((sMask[L * 3 + 0] | ((L < 32) ? (1u << L) : 0u)) & wmask(U, 0)) | Dw0;
    unsigned t1 = ((sMask[L * 3 + 1] | ((L >= 32 && L < 64) ? (1u << (L & 31)) : 0u)) & wmask(U, 1)) | Dw1;
    unsigned t2 = ((sMask[L * 3 + 2] | ((L >= 64) ? (1u << (L & 31)) : 0u)) & wmask(U, 2)) | Dw2;
    if (U < 32) t0 |= 1u << U; else if (U < 64) t1 |= 1u << (U & 31); else t2 |= 1u << (U & 31);

    // compaction + lane-parallel per-target precompute of all scalar coefficients
    unsigned lm = (1u << lane) - 1u;
    int c0 = __popc(t0), c1 = __popc(t1);
    int nT = c0 + c1 + __popc(t2);
#pragma unroll
    for (int w = 0; w < 3; w++) {
        unsigned tw = (w == 0) ? t0 : ((w == 1) ? t1 : t2);
        unsigned bit = 1u << lane;
        if (tw & bit) {
            int base = (w > 0 ? c0 : 0) + (w > 1 ? c1 : 0);
            int pos = base + __popc(tw & lm);
            int m = (w << 5) + lane;
            bool isU = (m == U);
            unsigned Dww = (w == 0) ? Dw0 : ((w == 1) ? Dw1 : Dw2);
            bool inD  = !isU && ((Dww & bit) != 0);
            bool inNL = (m == L) || ((sMask[L * 3 + w] & bit) != 0);
            float sm = isU ? sU : (sS0[m] + (inD ? sS1d[m] : 0.f));
            float c  = (L == U) ? 0.f : (isU ? -sU : ((inNL ? sL0 : 0.f) - (inD ? sU : 0.f)));
            float coef = isU ? ((L == U) ? 2.f * sU : sU)
                             : ((inNL ? sL0 : 0.f) + (inD ? sU : 0.f));
            coef *= sm;
            int mpk = m | (inD ? 256 : 0) | (inNL ? 512 : 0);
            sMeta[warp][pos] = make_float4(sm, c, coef, __int_as_float(mpk));
        }
    }
    __syncwarp();

    // per-lane constants (float4 slice ln)
    int ln = lane & 15, h = lane >> 4;
    const float4* W14 = (const float4*)W1;
    float4 w2v = __ldg(&((const float4*)W2)[ln]);
    float4 paV = __ldg(&W14[64 * 16 + ln]);
    float4 pbV = __ldg(&W14[65 * 16 + ln]);
    float4 dv = make_float4(pbV.x - paV.x, pbV.y - paV.y, pbV.z - paV.z, pbV.w - paV.w);
    float4 yU = __ldg(&x04[U * 16 + ln]);
    yU.x += pbV.x; yU.y += pbV.y; yU.z += pbV.z; yU.w += pbV.w;
    if (L == U) { yU.x += paV.x; yU.y += paV.y; yU.z += paV.z; yU.w += paV.w; }

    const float4* p04 = (const float4*)g_P0;
    float acc1 = 0.f, acc2 = 0.f;
    int rounds = (nT + 1) >> 1;

    for (int r = 0; r < rounds; r++) {
        int idx = 2 * r + h;
        bool act = (idx < nT);
        float4 meta = sMeta[warp][act ? idx : 0];
        int mpk = __float_as_int(meta.w);
        int m = mpk & 127;
        bool isU = (m == U);
        bool inD = (mpk & 256) != 0;
        bool inNL = (mpk & 512) != 0;

        float4 P = make_float4(0.f, 0.f, 0.f, 0.f);
        if (!isU) P = __ldg(&p04[(U * NN + m) * 16 + ln]);

        // scale-bump corrections over b in Nbar(m) ∩ D (s1-s0), +s0 if m==U (full s1 weight)
        int mw = m >> 5;
        unsigned mb = 1u << (m & 31);
#pragma unroll
        for (int w = 0; w < 3; w++) {
            unsigned cm = sMask[m * 3 + w] | ((mw == w) ? mb : 0u);
            cm &= (w == 0) ? Dw0 : ((w == 1) ? Dw1 : Dw2);
            while (cm) {
                int bb = __ffs(cm) - 1;
                cm &= cm - 1;
                bb += w << 5;
                float wt = sS1d[bb] + (isU ? sS0[bb] : 0.f);
                float4 xb = ((const float4*)sX)[bb * 16 + ln];
                P.x += wt * xb.x; P.y += wt * xb.y; P.z += wt * xb.z; P.w += wt * xb.w;
            }
        }

        if (L != U && !isU && inNL) {   // node L's w64 perturbation (scale s0_L)
            P.x += sL0 * paV.x; P.y += sL0 * paV.y; P.z += sL0 * paV.z; P.w += sL0 * paV.w;
        }
        if (isU || inD) {               // U term: s_U * y_U
            P.x += sU * yU.x; P.y += sU * yU.y; P.z += sU * yU.z; P.w += sU * yU.w;
        }

        float sm = meta.x, c = meta.y;

        // per-lane partial g (reduction deferred to warp end)
        float g1 = fmaxf(sm * P.x, 0.f) * w2v.x + fmaxf(sm * P.y, 0.f) * w2v.y
                 + fmaxf(sm * P.z, 0.f) * w2v.z + fmaxf(sm * P.w, 0.f) * w2v.w;
        float g2 = fmaxf(sm * (P.x + c * dv.x), 0.f) * w2v.x
                 + fmaxf(sm * (P.y + c * dv.y), 0.f) * w2v.y
                 + fmaxf(sm * (P.z + c * dv.z), 0.f) * w2v.z
                 + fmaxf(sm * (P.w + c * dv.w), 0.f) * w2v.w;

        float coef = act ? meta.z : 0.f;
        acc1 += coef * g1;
        acc2 += coef * g2;
    }

    // single full-warp reduction (sums 16 lanes per half AND both halves' targets)
#pragma unroll
    for (int off = 16; off; off >>= 1) {
        acc1 += __shfl_xor_sync(0xffffffffu, acc1, off);
        acc2 += __shfl_xor_sync(0xffffffffu, acc2, off);
    }
    if (lane == 0) {
        out[L * NN + U] = acc1;
        out[U * NN + L] = acc2;
    }
}

extern "C" void kernel_launch(void* const* d_in, const int* in_sizes, int n_in,
                              void* d_out, int out_size) {
    const float* z   = (const float*)d_in[0];
    const float* adj = (const float*)d_in[1];
    const float* W1  = (const float*)d_in[2];
    const float* W2  = (const float*)d_in[3];
    float* out = (float*)d_out;

    setup_kernel<<<2 * NN, NN>>>(z, W1, adj);
    setup_p0_kernel<<<2 * NN, TPB>>>();
    pair_kernel<<<NCHUNK, TPB>>>(W1, W2, out);
}

// round 15
// speedup vs baseline: 1.1939x; 1.0437x over previous
#include <cuda_runtime.h>
#include <cstdint>

#define NN 96
#define DD 64
#define TPB 256
#define NCHUNK 624   // sum over U of ceil((U+1)/8)
#define MAXT 60      // max targets per pair (deg_L+nD+2 << 60 for p=0.1 graphs)

// Scratch (allocation-free rule): device globals, recomputed deterministically every launch.
__device__ float g_X0[NN * DD];                        // z @ W1[:64]
__device__ float g_P0[NN * NN * DD];                   // [U][m][64]: base pre-activations
__device__ unsigned g_mask[NN * 3];                    // adjacency bitmask rows
__device__ __align__(16) unsigned char g_nbr[NN * NN]; // sorted neighbor lists

// bits [0, n) of 32-bit word w
__device__ __forceinline__ unsigned wmask(int n, int w) {
    int m = n - (w << 5);
    if (m <= 0) return 0u;
    if (m >= 32) return 0xffffffffu;
    return (1u << m) - 1u;
}

// cumulative chunk count before U: U=8a+r -> (a+1)(4a+r)
__device__ __forceinline__ int cumc(int U) {
    int a = U >> 3, r = U & 7;
    return (a + 1) * (4 * a + r);
}

// blocks 0..95: X0 row; blocks 96..191: adjacency row (parallel compaction)
__global__ void setup_kernel(const float* __restrict__ z, const float* __restrict__ W1,
                             const float* __restrict__ adj) {
    if (blockIdx.x < NN) {
        int row = blockIdx.x, c = threadIdx.x;
        __shared__ float zr[DD];
        if (c < DD) zr[c] = z[row * DD + c];
        __syncthreads();
        if (c < DD) {
            float acc = 0.f;
#pragma unroll
            for (int k = 0; k < DD; k++) acc += zr[k] * W1[k * DD + c];
            g_X0[row * DD + c] = acc;
        }
    } else {
        int row = blockIdx.x - NN;
        int t = threadIdx.x;
        __shared__ unsigned smk[3];
        __shared__ unsigned char snb[NN];
        bool f = (adj[row * NN + t] != 0.0f);
        unsigned bal = __ballot_sync(0xffffffffu, f);
        if ((t & 31) == 0) { smk[t >> 5] = bal; g_mask[row * 3 + (t >> 5)] = bal; }
        snb[t] = 96;
        __syncthreads();
        unsigned m0 = smk[0], m1 = smk[1], m2 = smk[2];
        int w = t >> 5, l = t & 31;
        unsigned lm = (1u << l) - 1u;
        unsigned mw = (w == 0) ? m0 : ((w == 1) ? m1 : m2);
        int off = ((w > 0) ? __popc(m0) : 0) + ((w > 1) ? __popc(m1) : 0) + __popc(mw & lm);
        if (f) snb[off] = (unsigned char)t;
        __syncthreads();
        g_nbr[row * NN + t] = snb[t];
    }
}

// 2 blocks per U: P0[U][m] = sum_{b in Nbar(m) ∩ [0,U)} s0_b * x_b, for m < U.
__global__ void __launch_bounds__(TPB) setup_p0_kernel() {
    int U = blockIdx.x >> 1;
    int half = blockIdx.x & 1;
    __shared__ float yb[(NN + 1) * DD];   // s0_b * x_b for b<U, zero rows >= U and 96
    __shared__ float sS[NN];
    __shared__ unsigned sMask[NN * 3];
    int tid = threadIdx.x;
    int ln = tid & 15, hw = tid >> 4;

    for (int q = tid; q < NN * 3; q += TPB) sMask[q] = g_mask[q];
    __syncthreads();
    if (tid < NN) {
        int deg = 1 + __popc(sMask[tid * 3] & wmask(U, 0))
                    + __popc(sMask[tid * 3 + 1] & wmask(U, 1))
                    + __popc(sMask[tid * 3 + 2] & wmask(U, 2));
        sS[tid] = rsqrtf((float)deg);
    }
    __syncthreads();
    const float4* x04 = (const float4*)g_X0;
    for (int q = tid; q < (NN + 1) * 16; q += TPB) {
        int row = q >> 4;
        float4 v = make_float4(0.f, 0.f, 0.f, 0.f);
        if (row < U) {
            v = x04[q];
            float s = sS[row];
            v.x *= s; v.y *= s; v.z *= s; v.w *= s;
        }
        ((float4*)yb)[q] = v;
    }
    __syncthreads();

    const float4* yb4 = (const float4*)yb;
    float4* p04 = (float4*)g_P0;
    for (int m = hw + (half << 4); m < U; m += 32) {
        int cnt = __popc(sMask[m * 3] & wmask(U, 0))
                + __popc(sMask[m * 3 + 1] & wmask(U, 1))
                + __popc(sMask[m * 3 + 2] & wmask(U, 2));
        float4 a = yb4[m * 16 + ln];   // self term
        const unsigned char* lst = &g_nbr[m * NN];
        int c4 = (cnt + 3) & ~3;
        for (int q = 0; q < c4; q += 4) {
            unsigned pk = *(const unsigned*)(lst + q);   // entries >= cnt hit zero rows
            float4 y0 = yb4[((pk & 255u) << 4) + ln];
            a.x += y0.x; a.y += y0.y; a.z += y0.z; a.w += y0.w;
            float4 y1 = yb4[(((pk >> 8) & 255u) << 4) + ln];
            a.x += y1.x; a.y += y1.y; a.z += y1.z; a.w += y1.w;
            float4 y2 = yb4[(((pk >> 16) & 255u) << 4) + ln];
            a.x += y2.x; a.y += y2.y; a.z += y2.z; a.w += y2.w;
            float4 y3 = yb4[((pk >> 24) << 4) + ln];
            a.x += y3.x; a.y += y3.y; a.z += y3.z; a.w += y3.w;
        }
        p04[(U * NN + m) * 16 + ln] = a;
    }
}

// One CTA per (U, 8-L chunk); one warp per pair (L,U). Layer 2 fused inline.
// Hot loop fully de-scalarized: meta carries sm/c/coef/off + prebuilt correction
// masks + flags; U-target folded into a per-warp register vector PU.
__global__ void __launch_bounds__(TPB) pair_kernel(const float* __restrict__ W1,
                                                   const float* __restrict__ W2,
                                                   float* __restrict__ out) {
    __shared__ unsigned sMask[NN * 3];
    __shared__ float sS0[NN], sS1d[NN];
    __shared__ float sX[NN * DD];            // x rows staged for b in N(U)∩[0,U), b-indexed
    __shared__ float4 sMetaA[8][MAXT];       // (sm, c, coef, off-as-int)
    __shared__ uint4  sMetaB[8][MAXT];       // (cm0, cm1, cm2, flags)

    // block -> (U, Lbase); reversed so heavy chunks first
    int b = (NCHUNK - 1) - (int)blockIdx.x;
    int a0 = (int)(sqrtf((float)b) * 0.5f);
    int U = 8 * a0;
    if (U > 95) U = 95;
    while (U < 95 && cumc(U + 1) <= b) ++U;
    while (U > 0 && cumc(U) > b) --U;
    int Lbase = (b - cumc(U)) * 8;

    int tid = threadIdx.x;
    int lane = tid & 31, warp = tid >> 5;

    for (int q = tid; q < NN * 3; q += TPB) sMask[q] = g_mask[q];
    __syncthreads();

    unsigned uw0 = sMask[U * 3 + 0] & wmask(U, 0);
    unsigned uw1 = sMask[U * 3 + 1] & wmask(U, 1);
    unsigned uw2 = sMask[U * 3 + 2] & wmask(U, 2);
    int cntU = __popc(uw0) + __popc(uw1) + __popc(uw2);

    if (tid < NN) {
        int m = tid;
        int deg = 1 + __popc(sMask[m * 3] & wmask(U, 0))
                    + __popc(sMask[m * 3 + 1] & wmask(U, 1))
                    + __popc(sMask[m * 3 + 2] & wmask(U, 2));
        float s0 = rsqrtf((float)deg);
        sS0[m] = s0;
        sS1d[m] = rsqrtf((float)(deg + 1)) - s0;
    }
    // stage x rows for b in N(U)∩[0,U)  (covers every warp's D set)
    const float4* x04 = (const float4*)g_X0;
    for (int q = tid >> 4; q < cntU; q += 16) {
        int bb = g_nbr[U * NN + q];
        ((float4*)sX)[bb * 16 + (tid & 15)] = x04[bb * 16 + (tid & 15)];
    }
    __syncthreads();

    int L = Lbase + warp;
    if (L > U) return;

    // ---- per-warp pair (L, U) ----
    unsigned Dw0 = sMask[U * 3 + 0] & wmask(L, 0);
    unsigned Dw1 = sMask[U * 3 + 1] & wmask(L, 1);
    unsigned Dw2 = sMask[U * 3 + 2] & wmask(L, 2);
    int nD = __popc(Dw0) + __popc(Dw1) + __popc(Dw2);
    float sU = rsqrtf(1.0f + (float)nD);
    float sL0 = sS0[L];

    // per-lane constants (float4 slice ln)
    int ln = lane & 15, h = lane >> 4;
    const float4* W14 = (const float4*)W1;
    float4 w2v = __ldg(&((const float4*)W2)[ln]);
    float4 paV = __ldg(&W14[64 * 16 + ln]);
    float4 pbV = __ldg(&W14[65 * 16 + ln]);
    float4 dv = make_float4(pbV.x - paV.x, pbV.y - paV.y, pbV.z - paV.z, pbV.w - paV.w);
    float4 yU = __ldg(&x04[U * 16 + ln]);
    yU.x += pbV.x; yU.y += pbV.y; yU.z += pbV.z; yU.w += pbV.w;
    if (L == U) { yU.x += paV.x; yU.y += paV.y; yU.z += paV.z; yU.w += paV.w; }

    // fold the U-target completely: PU = sum_{b in D} s1_b x_b  +  sU*yU
    float4 PU = make_float4(0.f, 0.f, 0.f, 0.f);
#pragma unroll
    for (int w = 0; w < 3; w++) {
        unsigned dm = (w == 0) ? Dw0 : ((w == 1) ? Dw1 : Dw2);
        while (dm) {
            int bb = __ffs(dm) - 1;
            dm &= dm - 1;
            bb += w << 5;
            float wt = sS1d[bb] + sS0[bb];
            float4 xb = ((const float4*)sX)[bb * 16 + ln];
            PU.x += wt * xb.x; PU.y += wt * xb.y; PU.z += wt * xb.z; PU.w += wt * xb.w;
        }
    }
    PU.x += sU * yU.x; PU.y += sU * yU.y; PU.z += sU * yU.z; PU.w += sU * yU.w;

    // target words: (Nbar(L)∩[0,U)) ∪ D ∪ {U}
    unsigned t0 = ((sMask[L * 3 + 0] | ((L < 32) ? (1u << L) : 0u)) & wmask(U, 0)) | Dw0;
    unsigned t1 = ((sMask[L * 3 + 1] | ((L >= 32 && L < 64) ? (1u << (L & 31)) : 0u)) & wmask(U, 1)) | Dw1;
    unsigned t2 = ((sMask[L * 3 + 2] | ((L >= 64) ? (1u << (L & 31)) : 0u)) & wmask(U, 2)) | Dw2;
    if (U < 32) t0 |= 1u << U; else if (U < 64) t1 |= 1u << (U & 31); else t2 |= 1u << (U & 31);

    // compaction + lane-parallel precompute of everything scalar / mask-shaped
    unsigned lm = (1u << lane) - 1u;
    int c0 = __popc(t0), c1 = __popc(t1);
    int nT = c0 + c1 + __popc(t2);
#pragma unroll
    for (int w = 0; w < 3; w++) {
        unsigned tw = (w == 0) ? t0 : ((w == 1) ? t1 : t2);
        unsigned bit = 1u << lane;
        if (tw & bit) {
            int base = (w > 0 ? c0 : 0) + (w > 1 ? c1 : 0);
            int pos = base + __popc(tw & lm);
            int m = (w << 5) + lane;
            bool isU = (m == U);
            unsigned Dww = (w == 0) ? Dw0 : ((w == 1) ? Dw1 : Dw2);
            bool inD  = !isU && ((Dww & bit) != 0);
            bool inNL = (m == L) || ((sMask[L * 3 + w] & bit) != 0);
            float sm = isU ? sU : (sS0[m] + (inD ? sS1d[m] : 0.f));
            float c  = (L == U) ? 0.f : (isU ? -sU : ((inNL ? sL0 : 0.f) - (inD ? sU : 0.f)));
            float coef = isU ? ((L == U) ? 2.f * sU : sU)
                             : ((inNL ? sL0 : 0.f) + (inD ? sU : 0.f));
            coef *= sm;
            int off = isU ? -1 : (U * NN + m) * 16;
            unsigned cm0 = 0, cm1 = 0, cm2 = 0, flags = 0;
            if (!isU) {
                cm0 = (sMask[m * 3 + 0] | ((w == 0) ? bit : 0u)) & Dw0;
                cm1 = (sMask[m * 3 + 1] | ((w == 1) ? bit : 0u)) & Dw1;
                cm2 = (sMask[m * 3 + 2] | ((w == 2) ? bit : 0u)) & Dw2;
                flags = (inD ? 1u : 0u) | ((inNL && L != U) ? 2u : 0u);
            }
            sMetaA[warp][pos] = make_float4(sm, c, coef, __int_as_float(off));
            sMetaB[warp][pos] = make_uint4(cm0, cm1, cm2, flags);
        }
    }
    __syncwarp();

    const float4* p04 = (const float4*)g_P0;
    float acc1 = 0.f, acc2 = 0.f;
    int rounds = (nT + 1) >> 1;

    for (int r = 0; r < rounds; r++) {
        int idx = 2 * r + h;
        bool act = (idx < nT);
        int ix = act ? idx : 0;
        float4 ma = sMetaA[warp][ix];
        uint4  mb = sMetaB[warp][ix];
        int off = __float_as_int(ma.w);

        float4 P;
        if (off >= 0) P = __ldg(&p04[off + ln]);
        else          P = PU;

        // corrections: prebuilt masks, weight = s1d_b always
        unsigned cm = mb.x;
        while (cm) {
            int bb = __ffs(cm) - 1; cm &= cm - 1;
            float4 xb = ((const float4*)sX)[bb * 16 + ln];
            float wt = sS1d[bb];
            P.x += wt * xb.x; P.y += wt * xb.y; P.z += wt * xb.z; P.w += wt * xb.w;
        }
        cm = mb.y;
        while (cm) {
            int bb = __ffs(cm) + 31; cm &= cm - 1;
            float4 xb = ((const float4*)sX)[bb * 16 + ln];
            float wt = sS1d[bb];
            P.x += wt * xb.x; P.y += wt * xb.y; P.z += wt * xb.z; P.w += wt * xb.w;
        }
        cm = mb.z;
        while (cm) {
            int bb = __ffs(cm) + 63; cm &= cm - 1;
            float4 xb = ((const float4*)sX)[bb * 16 + ln];
            float wt = sS1d[bb];
            P.x += wt * xb.x; P.y += wt * xb.y; P.z += wt * xb.z; P.w += wt * xb.w;
        }
        if (mb.w & 2u) {   // node L's w64 perturbation (scale s0_L)
            P.x += sL0 * paV.x; P.y += sL0 * paV.y; P.z += sL0 * paV.z; P.w += sL0 * paV.w;
        }
        if (mb.w & 1u) {   // U term: s_U * y_U (non-U targets in D)
            P.x += sU * yU.x; P.y += sU * yU.y; P.z += sU * yU.z; P.w += sU * yU.w;
        }

        float sm = ma.x, c = ma.y;

        float g1 = fmaxf(sm * P.x, 0.f) * w2v.x + fmaxf(sm * P.y, 0.f) * w2v.y
                 + fmaxf(sm * P.z, 0.f) * w2v.z + fmaxf(sm * P.w, 0.f) * w2v.w;
        float g2 = fmaxf(sm * (P.x + c * dv.x), 0.f) * w2v.x
                 + fmaxf(sm * (P.y + c * dv.y), 0.f) * w2v.y
                 + fmaxf(sm * (P.z + c * dv.z), 0.f) * w2v.z
                 + fmaxf(sm * (P.w + c * dv.w), 0.f) * w2v.w;

        float coef = act ? ma.z : 0.f;
        acc1 += coef * g1;
        acc2 += coef * g2;
    }

    // single full-warp reduction (sums 16 lanes per half AND both halves' targets)
#pragma unroll
    for (int off = 16; off; off >>= 1) {
        acc1 += __shfl_xor_sync(0xffffffffu, acc1, off);
        acc2 += __shfl_xor_sync(0xffffffffu, acc2, off);
    }
    if (lane == 0) {
        out[L * NN + U] = acc1;
        out[U * NN + L] = acc2;
    }
}

extern "C" void kernel_launch(void* const* d_in, const int* in_sizes, int n_in,
                              void* d_out, int out_size) {
    const float* z   = (const float*)d_in[0];
    const float* adj = (const float*)d_in[1];
    const float* W1  = (const float*)d_in[2];
    const float* W2  = (const float*)d_in[3];
    float* out = (float*)d_out;

    setup_kernel<<<2 * NN, NN>>>(z, W1, adj);
    setup_p0_kernel<<<2 * NN, TPB>>>();
    pair_kernel<<<NCHUNK, TPB>>>(W1, W2, out);
}